// round 1
// baseline (speedup 1.0000x reference)
#include <cuda_runtime.h>
#include <stdint.h>

// ---------------------------------------------------------------------------
// BoltzmannGateSTE: keep top-k (k = int(n/e)) elements by |x|, zero the rest.
// Exact k-th-largest |x| found via 2-level radix select on abs bit patterns:
//   level 1: top 12 bits (4096 buckets, smem hist + global merge)
//   level 2: remaining 19 bits (512K-bucket global hist, boundary elems only)
// Then elementwise mask pass. All scratch in __device__ globals (no allocs).
// ---------------------------------------------------------------------------

#define NCOARSE 4096
#define NFINE   (1 << 19)
#define NSUPER  512           // NFINE / 1024

__device__ unsigned g_coarse[NCOARSE];
__device__ unsigned g_fine[NFINE];
__device__ unsigned g_super[NSUPER];
__device__ unsigned g_bucket;   // coarse boundary bucket b*
__device__ unsigned g_krem;     // residual rank inside b*
__device__ unsigned g_tbits;    // exact abs-bits of k-th largest |x|

// ---------------- zero scratch (must run each replay) ----------------------
__global__ void zero_hists() {
    int idx = blockIdx.x * blockDim.x + threadIdx.x;
    int stride = gridDim.x * blockDim.x;
    for (int i = idx; i < NFINE; i += stride) g_fine[i] = 0;
    for (int i = idx; i < NCOARSE; i += stride) g_coarse[i] = 0;
}

// ---------------- pass 1: coarse histogram (top 12 abs bits) ---------------
__global__ void coarse_hist(const float4* __restrict__ x, int n4) {
    __shared__ unsigned sh[NCOARSE];
    for (int i = threadIdx.x; i < NCOARSE; i += blockDim.x) sh[i] = 0;
    __syncthreads();
    int idx = blockIdx.x * blockDim.x + threadIdx.x;
    int stride = gridDim.x * blockDim.x;
    for (int i = idx; i < n4; i += stride) {
        float4 v = x[i];
        atomicAdd(&sh[(__float_as_uint(v.x) & 0x7FFFFFFFu) >> 19], 1u);
        atomicAdd(&sh[(__float_as_uint(v.y) & 0x7FFFFFFFu) >> 19], 1u);
        atomicAdd(&sh[(__float_as_uint(v.z) & 0x7FFFFFFFu) >> 19], 1u);
        atomicAdd(&sh[(__float_as_uint(v.w) & 0x7FFFFFFFu) >> 19], 1u);
    }
    __syncthreads();
    for (int i = threadIdx.x; i < NCOARSE; i += blockDim.x) {
        unsigned c = sh[i];
        if (c) atomicAdd(&g_coarse[i], c);
    }
}

// ---------------- scan coarse hist from top; find boundary bucket ----------
// Single block, 1024 threads. Thread t owns buckets [4t .. 4t+3].
__global__ void coarse_scan(unsigned k) {
    __shared__ unsigned s[1024];
    const int t = threadIdx.x;
    unsigned c0 = g_coarse[4 * t + 0];
    unsigned c1 = g_coarse[4 * t + 1];
    unsigned c2 = g_coarse[4 * t + 2];
    unsigned c3 = g_coarse[4 * t + 3];
    s[t] = c0 + c1 + c2 + c3;
    __syncthreads();
    // inclusive suffix sum across threads
    for (int off = 1; off < 1024; off <<= 1) {
        unsigned add = (t + off < 1024) ? s[t + off] : 0u;
        __syncthreads();
        s[t] += add;
        __syncthreads();
    }
    unsigned above = (t < 1023) ? s[t + 1] : 0u;   // count in buckets > 4t+3
    // cumulative (from top) for this thread's 4 buckets, descending
    unsigned cum3 = above + c3;
    unsigned cum2 = cum3 + c2;
    unsigned cum1 = cum2 + c1;
    unsigned cum0 = cum1 + c0;
    if (cum3 >= k && above < k) { g_bucket = 4u * t + 3u; g_krem = k - above; }
    if (cum2 >= k && cum3  < k) { g_bucket = 4u * t + 2u; g_krem = k - cum3;  }
    if (cum1 >= k && cum2  < k) { g_bucket = 4u * t + 1u; g_krem = k - cum2;  }
    if (cum0 >= k && cum1  < k) { g_bucket = 4u * t + 0u; g_krem = k - cum1;  }
}

// ---------------- pass 2: fine histogram (low 19 bits, boundary only) ------
__global__ void fine_hist(const float4* __restrict__ x, int n4) {
    const unsigned b = g_bucket;
    int idx = blockIdx.x * blockDim.x + threadIdx.x;
    int stride = gridDim.x * blockDim.x;
    for (int i = idx; i < n4; i += stride) {
        float4 v = x[i];
        unsigned ux = __float_as_uint(v.x) & 0x7FFFFFFFu;
        unsigned uy = __float_as_uint(v.y) & 0x7FFFFFFFu;
        unsigned uz = __float_as_uint(v.z) & 0x7FFFFFFFu;
        unsigned uw = __float_as_uint(v.w) & 0x7FFFFFFFu;
        if ((ux >> 19) == b) atomicAdd(&g_fine[ux & 0x7FFFFu], 1u);
        if ((uy >> 19) == b) atomicAdd(&g_fine[uy & 0x7FFFFu], 1u);
        if ((uz >> 19) == b) atomicAdd(&g_fine[uz & 0x7FFFFu], 1u);
        if ((uw >> 19) == b) atomicAdd(&g_fine[uw & 0x7FFFFu], 1u);
    }
}

// ---------------- reduce fine hist into 512 super-buckets ------------------
__global__ void fine_super() {   // grid 512, block 256, 4 entries/thread
    __shared__ unsigned red[256];
    int base = blockIdx.x * 1024 + threadIdx.x * 4;
    unsigned v = g_fine[base] + g_fine[base + 1] + g_fine[base + 2] + g_fine[base + 3];
    red[threadIdx.x] = v;
    __syncthreads();
    for (int off = 128; off > 0; off >>= 1) {
        if (threadIdx.x < off) red[threadIdx.x] += red[threadIdx.x + off];
        __syncthreads();
    }
    if (threadIdx.x == 0) g_super[blockIdx.x] = red[0];
}

// ---------------- final scan: exact threshold bits -------------------------
// Single block, 1024 threads.
__global__ void fine_scan() {
    __shared__ unsigned s[1024];
    __shared__ unsigned sh_super, sh_krem2;
    const int t = threadIdx.x;
    const unsigned krem = g_krem;

    // phase 1: suffix scan over 512 super sums
    s[t] = (t < NSUPER) ? g_super[t] : 0u;
    __syncthreads();
    for (int off = 1; off < 1024; off <<= 1) {
        unsigned add = (t + off < 1024) ? s[t + off] : 0u;
        __syncthreads();
        s[t] += add;
        __syncthreads();
    }
    if (t < NSUPER) {
        unsigned cum  = s[t];
        unsigned next = (t + 1 < NSUPER) ? s[t + 1] : 0u;
        if (cum >= krem && next < krem) { sh_super = (unsigned)t; sh_krem2 = krem - next; }
    }
    __syncthreads();
    const unsigned sb = sh_super;
    const unsigned krem2 = sh_krem2;

    // phase 2: suffix scan over the 1024 fine entries of super-bucket sb
    unsigned c = g_fine[sb * 1024 + t];
    __syncthreads();
    s[t] = c;
    __syncthreads();
    for (int off = 1; off < 1024; off <<= 1) {
        unsigned add = (t + off < 1024) ? s[t + off] : 0u;
        __syncthreads();
        s[t] += add;
        __syncthreads();
    }
    {
        unsigned cum  = s[t];
        unsigned next = (t < 1023) ? s[t + 1] : 0u;
        if (cum >= krem2 && next < krem2) {
            g_tbits = (g_bucket << 19) | (sb * 1024u + (unsigned)t);
        }
    }
}

// ---------------- pass 3: apply mask ---------------------------------------
__global__ void apply_mask(const float4* __restrict__ x, float4* __restrict__ out, int n4) {
    const unsigned tb = g_tbits;
    int idx = blockIdx.x * blockDim.x + threadIdx.x;
    int stride = gridDim.x * blockDim.x;
    for (int i = idx; i < n4; i += stride) {
        float4 v = x[i];
        v.x = ((__float_as_uint(v.x) & 0x7FFFFFFFu) >= tb) ? v.x : 0.0f;
        v.y = ((__float_as_uint(v.y) & 0x7FFFFFFFu) >= tb) ? v.y : 0.0f;
        v.z = ((__float_as_uint(v.z) & 0x7FFFFFFFu) >= tb) ? v.z : 0.0f;
        v.w = ((__float_as_uint(v.w) & 0x7FFFFFFFu) >= tb) ? v.w : 0.0f;
        out[i] = v;
    }
}

__global__ void copy_all(const float4* __restrict__ x, float4* __restrict__ out, int n4) {
    int idx = blockIdx.x * blockDim.x + threadIdx.x;
    int stride = gridDim.x * blockDim.x;
    for (int i = idx; i < n4; i += stride) out[i] = x[i];
}

extern "C" void kernel_launch(void* const* d_in, const int* in_sizes, int n_in,
                              void* d_out, int out_size) {
    const float* x = (const float*)d_in[0];
    float* out = (float*)d_out;
    int n = in_sizes[0];

    // k = max(1, int(n * (1.0/e))) — bit-exact replication of the Python.
    const double FRACTION = 1.0 / 2.718281828459045235360287;
    long long kll = (long long)((double)n * FRACTION);
    if (kll < 1) kll = 1;

    int n4 = n / 4;   // n = 33,554,432 is divisible by 4
    const int BLK = 256;
    const int GRID_BIG = 1184;  // 148 SMs * 8 blocks

    if (kll >= (long long)n) {
        copy_all<<<GRID_BIG, BLK>>>((const float4*)x, (float4*)out, n4);
        return;
    }
    unsigned k = (unsigned)kll;

    zero_hists<<<256, 256>>>();
    coarse_hist<<<GRID_BIG, BLK>>>((const float4*)x, n4);
    coarse_scan<<<1, 1024>>>(k);
    fine_hist<<<GRID_BIG, BLK>>>((const float4*)x, n4);
    fine_super<<<NSUPER, 256>>>();
    fine_scan<<<1, 1024>>>();
    apply_mask<<<GRID_BIG, BLK>>>((const float4*)x, (float4*)out, n4);
}

// round 2
// speedup vs baseline: 1.0304x; 1.0304x over previous
#include <cuda_runtime.h>
#include <stdint.h>

// ---------------------------------------------------------------------------
// BoltzmannGateSTE: keep top-k (k = int(n/e)) elements by |x|, zero the rest.
// Exact k-th |x| via 2-level radix select on abs bit patterns.
//   pass A: coarse hist of top 12 abs bits (read 128 MB)
//   pass B (FUSED): fine hist of low 19 bits for boundary-bucket elems,
//           write decided outputs, compact undecided elems to a side list
//           (read 128 MB + write 128 MB + ~4.5 MB list)
//   fixup:  scatter-write boundary keepers from the list (~12 MB)
// ---------------------------------------------------------------------------

#define NCOARSE 4096
#define NFINE   (1 << 19)
#define NSUPER  512
#define LISTCAP (1 << 22)   // 4M entries (expected ~560K)
#define CAPB    2048        // per-block staging (expected ~470/block)

__device__ unsigned g_coarse[NCOARSE];
__device__ unsigned g_fine[NFINE];
__device__ unsigned g_super[NSUPER];
__device__ unsigned g_bucket;   // coarse boundary bucket b*
__device__ unsigned g_krem;     // residual rank inside b*
__device__ unsigned g_tbits;    // exact abs-bits of k-th largest |x|
__device__ unsigned g_listcnt;
__device__ unsigned g_overflow;
__device__ uint2    g_list[LISTCAP];   // {element index, raw float bits}

// ---------------- zero scratch (runs each replay) --------------------------
__global__ void zero_hists() {
    int idx = blockIdx.x * blockDim.x + threadIdx.x;
    int stride = gridDim.x * blockDim.x;
    for (int i = idx; i < NFINE; i += stride) g_fine[i] = 0;
    for (int i = idx; i < NCOARSE; i += stride) g_coarse[i] = 0;
    if (idx == 0) { g_listcnt = 0; g_overflow = 0; }
}

// ---------------- pass A: coarse histogram (top 12 abs bits) ---------------
__global__ void coarse_hist(const float4* __restrict__ x, int n4) {
    __shared__ unsigned sh[NCOARSE];
    for (int i = threadIdx.x; i < NCOARSE; i += blockDim.x) sh[i] = 0;
    __syncthreads();
    int idx = blockIdx.x * blockDim.x + threadIdx.x;
    int stride = gridDim.x * blockDim.x;
#define H(f) atomicAdd(&sh[(__float_as_uint(f) & 0x7FFFFFFFu) >> 19], 1u)
    int i = idx;
    for (; i + 3 * stride < n4; i += 4 * stride) {
        float4 v0 = x[i];
        float4 v1 = x[i + stride];
        float4 v2 = x[i + 2 * stride];
        float4 v3 = x[i + 3 * stride];
        H(v0.x); H(v0.y); H(v0.z); H(v0.w);
        H(v1.x); H(v1.y); H(v1.z); H(v1.w);
        H(v2.x); H(v2.y); H(v2.z); H(v2.w);
        H(v3.x); H(v3.y); H(v3.z); H(v3.w);
    }
    for (; i < n4; i += stride) {
        float4 v = x[i];
        H(v.x); H(v.y); H(v.z); H(v.w);
    }
#undef H
    __syncthreads();
    for (int j = threadIdx.x; j < NCOARSE; j += blockDim.x) {
        unsigned c = sh[j];
        if (c) atomicAdd(&g_coarse[j], c);
    }
}

// ---------------- scan coarse hist from top; find boundary bucket ----------
__global__ void coarse_scan(unsigned k) {
    __shared__ unsigned s[1024];
    const int t = threadIdx.x;
    unsigned c0 = g_coarse[4 * t + 0];
    unsigned c1 = g_coarse[4 * t + 1];
    unsigned c2 = g_coarse[4 * t + 2];
    unsigned c3 = g_coarse[4 * t + 3];
    s[t] = c0 + c1 + c2 + c3;
    __syncthreads();
    for (int off = 1; off < 1024; off <<= 1) {
        unsigned add = (t + off < 1024) ? s[t + off] : 0u;
        __syncthreads();
        s[t] += add;
        __syncthreads();
    }
    unsigned above = (t < 1023) ? s[t + 1] : 0u;
    unsigned cum3 = above + c3;
    unsigned cum2 = cum3 + c2;
    unsigned cum1 = cum2 + c1;
    unsigned cum0 = cum1 + c0;
    if (cum3 >= k && above < k) { g_bucket = 4u * t + 3u; g_krem = k - above; }
    if (cum2 >= k && cum3  < k) { g_bucket = 4u * t + 2u; g_krem = k - cum3;  }
    if (cum1 >= k && cum2  < k) { g_bucket = 4u * t + 1u; g_krem = k - cum2;  }
    if (cum0 >= k && cum1  < k) { g_bucket = 4u * t + 0u; g_krem = k - cum1;  }
}

// ---------------- warp-aggregated push into block staging buffer -----------
__device__ __forceinline__ void push_item(uint2* buf, unsigned* scnt,
                                          bool p, unsigned eidx, unsigned raw) {
    unsigned amask = __activemask();
    unsigned m = __ballot_sync(amask, p);
    if (m == 0) return;
    int lane = threadIdx.x & 31;
    int leader = __ffs(m) - 1;
    unsigned pos = 0;
    if (lane == leader) pos = atomicAdd(scnt, (unsigned)__popc(m));
    pos = __shfl_sync(amask, pos, leader);
    pos += (unsigned)__popc(m & ((1u << lane) - 1u));
    if (p && pos < CAPB) { buf[pos].x = eidx; buf[pos].y = raw; }
}

// ---------------- pass B: fused fine-hist + decided-output + compaction ----
__global__ void fused_pass(const float4* __restrict__ x, float4* __restrict__ out, int n4) {
    __shared__ uint2 buf[CAPB];
    __shared__ unsigned scnt, sbase;
    if (threadIdx.x == 0) scnt = 0;
    __syncthreads();
    const unsigned b = g_bucket;
    int idx = blockIdx.x * blockDim.x + threadIdx.x;
    int stride = gridDim.x * blockDim.x;

#define DO4(vv, fi) { \
    unsigned r0 = __float_as_uint(vv.x), r1 = __float_as_uint(vv.y); \
    unsigned r2 = __float_as_uint(vv.z), r3 = __float_as_uint(vv.w); \
    unsigned u0 = r0 & 0x7FFFFFFFu, u1 = r1 & 0x7FFFFFFFu; \
    unsigned u2 = r2 & 0x7FFFFFFFu, u3 = r3 & 0x7FFFFFFFu; \
    unsigned c0 = u0 >> 19, c1 = u1 >> 19, c2 = u2 >> 19, c3 = u3 >> 19; \
    float4 o; \
    o.x = (c0 > b) ? vv.x : 0.0f; \
    o.y = (c1 > b) ? vv.y : 0.0f; \
    o.z = (c2 > b) ? vv.z : 0.0f; \
    o.w = (c3 > b) ? vv.w : 0.0f; \
    out[fi] = o; \
    bool p0 = (c0 == b), p1 = (c1 == b), p2 = (c2 == b), p3 = (c3 == b); \
    if (p0) atomicAdd(&g_fine[u0 & 0x7FFFFu], 1u); \
    if (p1) atomicAdd(&g_fine[u1 & 0x7FFFFu], 1u); \
    if (p2) atomicAdd(&g_fine[u2 & 0x7FFFFu], 1u); \
    if (p3) atomicAdd(&g_fine[u3 & 0x7FFFFu], 1u); \
    unsigned eb = (unsigned)(fi) * 4u; \
    push_item(buf, &scnt, p0, eb + 0u, r0); \
    push_item(buf, &scnt, p1, eb + 1u, r1); \
    push_item(buf, &scnt, p2, eb + 2u, r2); \
    push_item(buf, &scnt, p3, eb + 3u, r3); \
}

    int i = idx;
    for (; i + 3 * stride < n4; i += 4 * stride) {
        float4 v0 = x[i];
        float4 v1 = x[i + stride];
        float4 v2 = x[i + 2 * stride];
        float4 v3 = x[i + 3 * stride];
        DO4(v0, i);
        DO4(v1, i + stride);
        DO4(v2, i + 2 * stride);
        DO4(v3, i + 3 * stride);
    }
    for (; i < n4; i += stride) {
        float4 v = x[i];
        DO4(v, i);
    }
#undef DO4

    // flush staging buffer to global list
    __syncthreads();
    if (threadIdx.x == 0) {
        unsigned c = scnt;
        if (c > CAPB) { c = CAPB; g_overflow = 1; }
        sbase = atomicAdd(&g_listcnt, c);
        if (sbase + c > LISTCAP) g_overflow = 1;
    }
    __syncthreads();
    unsigned c = scnt; if (c > CAPB) c = CAPB;
    unsigned base = sbase;
    for (unsigned j = threadIdx.x; j < c; j += blockDim.x) {
        if (base + j < LISTCAP) g_list[base + j] = buf[j];
    }
}

// ---------------- reduce fine hist into 512 super-buckets ------------------
__global__ void fine_super() {
    __shared__ unsigned red[256];
    int base = blockIdx.x * 1024 + threadIdx.x * 4;
    unsigned v = g_fine[base] + g_fine[base + 1] + g_fine[base + 2] + g_fine[base + 3];
    red[threadIdx.x] = v;
    __syncthreads();
    for (int off = 128; off > 0; off >>= 1) {
        if (threadIdx.x < off) red[threadIdx.x] += red[threadIdx.x + off];
        __syncthreads();
    }
    if (threadIdx.x == 0) g_super[blockIdx.x] = red[0];
}

// ---------------- final scan: exact threshold bits -------------------------
__global__ void fine_scan() {
    __shared__ unsigned s[1024];
    __shared__ unsigned sh_super, sh_krem2;
    const int t = threadIdx.x;
    const unsigned krem = g_krem;

    s[t] = (t < NSUPER) ? g_super[t] : 0u;
    __syncthreads();
    for (int off = 1; off < 1024; off <<= 1) {
        unsigned add = (t + off < 1024) ? s[t + off] : 0u;
        __syncthreads();
        s[t] += add;
        __syncthreads();
    }
    if (t < NSUPER) {
        unsigned cum  = s[t];
        unsigned next = (t + 1 < NSUPER) ? s[t + 1] : 0u;
        if (cum >= krem && next < krem) { sh_super = (unsigned)t; sh_krem2 = krem - next; }
    }
    __syncthreads();
    const unsigned sb = sh_super;
    const unsigned krem2 = sh_krem2;

    unsigned cfine = g_fine[sb * 1024 + t];
    __syncthreads();
    s[t] = cfine;
    __syncthreads();
    for (int off = 1; off < 1024; off <<= 1) {
        unsigned add = (t + off < 1024) ? s[t + off] : 0u;
        __syncthreads();
        s[t] += add;
        __syncthreads();
    }
    {
        unsigned cum  = s[t];
        unsigned next = (t < 1023) ? s[t + 1] : 0u;
        if (cum >= krem2 && next < krem2) {
            g_tbits = (g_bucket << 19) | (sb * 1024u + (unsigned)t);
        }
    }
}

// ---------------- fixup: scatter-write boundary keepers from list ----------
__global__ void fixup(float* __restrict__ out) {
    if (g_overflow) return;   // fallback kernel handles this case
    const unsigned tb = g_tbits;
    unsigned cnt = g_listcnt;
    if (cnt > LISTCAP) cnt = LISTCAP;
    unsigned idx = blockIdx.x * blockDim.x + threadIdx.x;
    unsigned stride = gridDim.x * blockDim.x;
    for (unsigned j = idx; j < cnt; j += stride) {
        uint2 e = g_list[j];
        if ((e.y & 0x7FFFFFFFu) >= tb) out[e.x] = __uint_as_float(e.y);
    }
}

// ---------------- fallback: full re-mask if staging overflowed -------------
__global__ void fallback_mask(const float4* __restrict__ x, float4* __restrict__ out, int n4) {
    if (!g_overflow) return;
    const unsigned tb = g_tbits;
    int idx = blockIdx.x * blockDim.x + threadIdx.x;
    int stride = gridDim.x * blockDim.x;
    for (int i = idx; i < n4; i += stride) {
        float4 v = x[i];
        v.x = ((__float_as_uint(v.x) & 0x7FFFFFFFu) >= tb) ? v.x : 0.0f;
        v.y = ((__float_as_uint(v.y) & 0x7FFFFFFFu) >= tb) ? v.y : 0.0f;
        v.z = ((__float_as_uint(v.z) & 0x7FFFFFFFu) >= tb) ? v.z : 0.0f;
        v.w = ((__float_as_uint(v.w) & 0x7FFFFFFFu) >= tb) ? v.w : 0.0f;
        out[i] = v;
    }
}

__global__ void copy_all(const float4* __restrict__ x, float4* __restrict__ out, int n4) {
    int idx = blockIdx.x * blockDim.x + threadIdx.x;
    int stride = gridDim.x * blockDim.x;
    for (int i = idx; i < n4; i += stride) out[i] = x[i];
}

extern "C" void kernel_launch(void* const* d_in, const int* in_sizes, int n_in,
                              void* d_out, int out_size) {
    const float* x = (const float*)d_in[0];
    float* out = (float*)d_out;
    int n = in_sizes[0];

    // k = max(1, int(n * (1.0/e))) — bit-exact replication of the Python.
    const double FRACTION = 1.0 / 2.718281828459045235360287;
    long long kll = (long long)((double)n * FRACTION);
    if (kll < 1) kll = 1;

    int n4 = n / 4;             // n = 33,554,432
    const int BLK = 256;
    const int GRID = 1024;      // 2^18 threads -> even division of n4 = 2^23

    if (kll >= (long long)n) {
        copy_all<<<GRID, BLK>>>((const float4*)x, (float4*)out, n4);
        return;
    }
    unsigned k = (unsigned)kll;

    zero_hists<<<512, 256>>>();
    coarse_hist<<<GRID, BLK>>>((const float4*)x, n4);
    coarse_scan<<<1, 1024>>>(k);
    fused_pass<<<GRID, BLK>>>((const float4*)x, (float4*)out, n4);
    fine_super<<<NSUPER, 256>>>();
    fine_scan<<<1, 1024>>>();
    fixup<<<512, 256>>>(out);
    fallback_mask<<<GRID, BLK>>>((const float4*)x, (float4*)out, n4);
}